// round 1
// baseline (speedup 1.0000x reference)
#include <cuda_runtime.h>
#include <math.h>

// ---------------- problem constants ----------------
#define BATCH     8
#define DMODEL    192
#define DINNER    384
#define DSTATE    16
#define HIMG      128
#define WIMG      128
#define LIMG      16384               // H*W
#define MROWS     131072              // BATCH * LIMG
#define NPROJ     768                 // 2*DINNER

// ---------------- scratch (static device memory; no allocs allowed) --------
__device__ float g_XI[(size_t)MROWS * DINNER];   // x_inner after proj     (201 MB)
__device__ float g_ZS[(size_t)MROWS * DINNER];   // silu(z) after proj     (201 MB)
__device__ float g_Y [(size_t)MROWS * DINNER];   // post-layernorm y       (201 MB)

// =====================================================================
// Kernel 1: x_proj = x @ w_in  ;  split -> XI (raw), ZS (silu applied)
// A: [131072,192] row-major (raw reinterpretation of NCHW input)
// B: [192,768]
// Tile: BM=64, BN=128, BK=16, 256 threads, 8x4 micro-tile.
// Thread map: mt=tid/32 (8), nt=tid%32 (32); m_i = bm+mt*8+i, n_j = bn+nt+j*32
// -> epilogue writes have lanes contiguous along n (coalesced).
// =====================================================================
#define G1_BM 64
#define G1_BN 128
#define G1_BK 16

__global__ void __launch_bounds__(256) gemm_proj_kernel(
    const float* __restrict__ A, const float* __restrict__ Bw)
{
    __shared__ float As[G1_BK][G1_BM + 1];
    __shared__ float Bs[G1_BK][G1_BN];

    const int tid = threadIdx.x;
    const int bm  = blockIdx.x * G1_BM;
    const int bn  = blockIdx.y * G1_BN;
    const int mt  = tid >> 5;    // 0..7
    const int nt  = tid & 31;    // 0..31

    float acc[8][4];
#pragma unroll
    for (int i = 0; i < 8; ++i)
#pragma unroll
        for (int j = 0; j < 4; ++j) acc[i][j] = 0.f;

    const int a_r = tid >> 2;          // 0..63
    const int a_c = (tid & 3) * 4;     // 0,4,8,12
    const int b_r = tid >> 5;          // 0..7
    const int b_c = (tid & 31) * 4;

    for (int k0 = 0; k0 < DMODEL; k0 += G1_BK) {
        float4 av = *(const float4*)(A + (size_t)(bm + a_r) * DMODEL + k0 + a_c);
        As[a_c + 0][a_r] = av.x;
        As[a_c + 1][a_r] = av.y;
        As[a_c + 2][a_r] = av.z;
        As[a_c + 3][a_r] = av.w;

        float4 bv0 = *(const float4*)(Bw + (size_t)(k0 + b_r) * NPROJ + bn + b_c);
        float4 bv1 = *(const float4*)(Bw + (size_t)(k0 + b_r + 8) * NPROJ + bn + b_c);
        *(float4*)&Bs[b_r][b_c]     = bv0;
        *(float4*)&Bs[b_r + 8][b_c] = bv1;
        __syncthreads();

#pragma unroll
        for (int k = 0; k < G1_BK; ++k) {
            float ra[8], rb[4];
#pragma unroll
            for (int i = 0; i < 8; ++i) ra[i] = As[k][mt * 8 + i];
#pragma unroll
            for (int j = 0; j < 4; ++j) rb[j] = Bs[k][nt + j * 32];
#pragma unroll
            for (int i = 0; i < 8; ++i)
#pragma unroll
                for (int j = 0; j < 4; ++j) acc[i][j] += ra[i] * rb[j];
        }
        __syncthreads();
    }

    // epilogue: n<384 -> XI, else silu -> ZS.  BN=128 divides 384 so the
    // branch is uniform per block column.
#pragma unroll
    for (int i = 0; i < 8; ++i) {
        const size_t m = (size_t)bm + mt * 8 + i;
#pragma unroll
        for (int j = 0; j < 4; ++j) {
            const int n = bn + nt + j * 32;
            float v = acc[i][j];
            if (n < DINNER) {
                g_XI[m * DINNER + n] = v;
            } else {
                float s = 1.f / (1.f + expf(-v));
                g_ZS[m * DINNER + (n - DINNER)] = v * s;
            }
        }
    }
}

// =====================================================================
// Kernel 2: fused depthwise conv3x3 + silu + SSM + gate + LayerNorm
// One warp processes one row r (= b*L + l).  384 channels -> 12 per lane.
// =====================================================================
#define CPL 12              // channels per lane
#define WARPS_PER_BLOCK 8
#define ROWS_PER_WARP 8

__global__ void __launch_bounds__(256) fused_ssm_kernel(
    const float* __restrict__ w_conv,   // [384,1,3,3]
    const float* __restrict__ b_conv,   // [384]
    const float* __restrict__ w_x,      // [384,32]
    const float* __restrict__ w_dt,     // [16,384]
    const float* __restrict__ b_dt,     // [384]
    const float* __restrict__ D_skip,   // [384]
    const float* __restrict__ gamma,    // [384]
    const float* __restrict__ beta)     // [384]
{
    extern __shared__ float sh[];
    float* wx_sh    = sh;                          // 384*32
    float* wdt_sh   = wx_sh    + 384 * 32;         // 16*384
    float* wconv_sh = wdt_sh   + 16 * 384;         // 384*9
    float* bconv_sh = wconv_sh + 384 * 9;          // 384
    float* bdt_sh   = bconv_sh + 384;              // 384
    float* dskip_sh = bdt_sh   + 384;              // 384
    float* gam_sh   = dskip_sh + 384;              // 384
    float* bet_sh   = gam_sh   + 384;              // 384
    float* xc_sh    = bet_sh   + 384;              // 8*384
    float* ssm_sh   = xc_sh    + WARPS_PER_BLOCK * 384;  // 8*32

    const int tid = threadIdx.x;
    for (int i = tid; i < 384 * 32; i += blockDim.x) wx_sh[i]    = w_x[i];
    for (int i = tid; i < 16 * 384; i += blockDim.x) wdt_sh[i]   = w_dt[i];
    for (int i = tid; i < 384 * 9;  i += blockDim.x) wconv_sh[i] = w_conv[i];
    for (int i = tid; i < 384;      i += blockDim.x) {
        bconv_sh[i] = b_conv[i];
        bdt_sh[i]   = b_dt[i];
        dskip_sh[i] = D_skip[i];
        gam_sh[i]   = gamma[i];
        bet_sh[i]   = beta[i];
    }
    __syncthreads();

    const int warp = tid >> 5;
    const int lane = tid & 31;
    const int gw   = blockIdx.x * WARPS_PER_BLOCK + warp;
    const size_t base_r = (size_t)gw * ROWS_PER_WARP;

    float* xc_w  = xc_sh  + warp * 384;
    float* ssm_w = ssm_sh + warp * 32;

    for (int it = 0; it < ROWS_PER_WARP; ++it) {
        const size_t r = base_r + it;
        const int l = (int)(r & (LIMG - 1));
        const int h = l >> 7;
        const int w = l & 127;

        // ---- 1. depthwise conv 3x3 + silu ----
        float xc_reg[CPL];
#pragma unroll
        for (int k = 0; k < CPL; ++k) {
            const int ch = lane + k * 32;
            float acc = bconv_sh[ch];
#pragma unroll
            for (int dy = -1; dy <= 1; ++dy) {
                const int hh = h + dy;
                if (hh < 0 || hh >= HIMG) continue;
#pragma unroll
                for (int dx = -1; dx <= 1; ++dx) {
                    const int ww = w + dx;
                    if (ww < 0 || ww >= WIMG) continue;
                    const size_t rr = r + (size_t)(dy * WIMG + dx);
                    acc += wconv_sh[ch * 9 + (dy + 1) * 3 + (dx + 1)]
                           * g_XI[rr * DINNER + ch];
                }
            }
            const float s = 1.f / (1.f + expf(-acc));
            const float v = acc * s;
            xc_reg[k] = v;
            xc_w[ch]  = v;
        }
        __syncwarp();

        // ---- 2. x_ssm: lane computes state s = lane (32 states) ----
        {
            float acc = 0.f;
#pragma unroll 8
            for (int ch = 0; ch < 384; ++ch)
                acc += xc_w[ch] * wx_sh[ch * 32 + lane];
            ssm_w[lane] = acc;
        }
        __syncwarp();

        // ---- 3. bc = sum_s B_s * C_s ----
        float bc = 0.f;
#pragma unroll
        for (int s = 0; s < DSTATE; ++s) bc += ssm_w[s] * ssm_w[DSTATE + s];

        // ---- 4. dt, gate, accumulate stats ----
        float yv[CPL];
        float sum = 0.f, sumsq = 0.f;
#pragma unroll
        for (int k = 0; k < CPL; ++k) {
            const int ch = lane + k * 32;
            float dv = bdt_sh[ch];
#pragma unroll
            for (int s = 0; s < DSTATE; ++s)
                dv += ssm_w[s] * wdt_sh[s * 384 + ch];
            const float dt = (dv > 20.f) ? dv : log1pf(expf(dv));
            const float zs = g_ZS[r * DINNER + ch];
            const float v  = (dt * bc + xc_reg[k] * dskip_sh[ch]) * zs;
            yv[k] = v;
            sum   += v;
            sumsq += v * v;
        }
#pragma unroll
        for (int o = 16; o; o >>= 1) {
            sum   += __shfl_xor_sync(0xffffffffu, sum, o);
            sumsq += __shfl_xor_sync(0xffffffffu, sumsq, o);
        }
        const float mu  = sum * (1.f / 384.f);
        const float var = sumsq * (1.f / 384.f) - mu * mu;
        const float rs  = rsqrtf(var + 1e-5f);

        // ---- 5. layernorm + store ----
#pragma unroll
        for (int k = 0; k < CPL; ++k) {
            const int ch = lane + k * 32;
            g_Y[r * DINNER + ch] = (yv[k] - mu) * rs * gam_sh[ch] + bet_sh[ch];
        }
    }
}

// =====================================================================
// Kernel 3: out = Y @ w_out, written transposed as [B, 192, L]
// Tile: BM=128, BN=64, BK=16, 256 threads.
// Thread map: mt=tid%32 (lane follows m/l), nt=tid/32 (8).
// m_i = bm+mt+i*32 (4), n_j = bn+nt*8+j (8) -> writes coalesced along l.
// =====================================================================
#define G3_BM 128
#define G3_BN 64
#define G3_BK 16

__global__ void __launch_bounds__(256) gemm_out_kernel(
    const float* __restrict__ Bw,   // w_out [384,192]
    float* __restrict__ OUT)        // [8,192,16384]
{
    __shared__ float As[G3_BK][G3_BM + 1];
    __shared__ float Bs[G3_BK][G3_BN + 1];

    const int tid = threadIdx.x;
    const size_t bm = (size_t)blockIdx.x * G3_BM;
    const int bn    = blockIdx.y * G3_BN;
    const int mt = tid & 31;
    const int nt = tid >> 5;

    float acc[4][8];
#pragma unroll
    for (int i = 0; i < 4; ++i)
#pragma unroll
        for (int j = 0; j < 8; ++j) acc[i][j] = 0.f;

    const int b_r = tid >> 4;           // 0..15
    const int b_c = (tid & 15) * 4;     // 0..60

    for (int k0 = 0; k0 < DINNER; k0 += G3_BK) {
        // A tile: 128 rows x 16 k, 8 floats per thread (2x float4)
#pragma unroll
        for (int t = 0; t < 2; ++t) {
            const int idx = tid * 2 + t;
            const int a_r = idx >> 2;
            const int a_c = (idx & 3) * 4;
            float4 av = *(const float4*)(g_Y + (bm + a_r) * DINNER + k0 + a_c);
            As[a_c + 0][a_r] = av.x;
            As[a_c + 1][a_r] = av.y;
            As[a_c + 2][a_r] = av.z;
            As[a_c + 3][a_r] = av.w;
        }
        // B tile: 16 x 64
        {
            float4 bv = *(const float4*)(Bw + (size_t)(k0 + b_r) * DMODEL + bn + b_c);
            Bs[b_r][b_c + 0] = bv.x;
            Bs[b_r][b_c + 1] = bv.y;
            Bs[b_r][b_c + 2] = bv.z;
            Bs[b_r][b_c + 3] = bv.w;
        }
        __syncthreads();

#pragma unroll
        for (int k = 0; k < G3_BK; ++k) {
            float ra[4], rb[8];
#pragma unroll
            for (int i = 0; i < 4; ++i) ra[i] = As[k][mt + i * 32];
#pragma unroll
            for (int j = 0; j < 8; ++j) rb[j] = Bs[k][nt * 8 + j];
#pragma unroll
            for (int i = 0; i < 4; ++i)
#pragma unroll
                for (int j = 0; j < 8; ++j) acc[i][j] += ra[i] * rb[j];
        }
        __syncthreads();
    }

    // transposed write: OUT[b][n][l]; lanes (mt) contiguous in l -> coalesced
#pragma unroll
    for (int i = 0; i < 4; ++i) {
        const size_t m = bm + mt + i * 32;
        const int b = (int)(m >> 14);         // / 16384
        const int l = (int)(m & 16383);
#pragma unroll
        for (int j = 0; j < 8; ++j) {
            const int n = bn + nt * 8 + j;
            OUT[((size_t)b * DMODEL + n) * LIMG + l] = acc[i][j];
        }
    }
}

// =====================================================================
extern "C" void kernel_launch(void* const* d_in, const int* in_sizes, int n_in,
                              void* d_out, int out_size) {
    (void)in_sizes; (void)n_in; (void)out_size;
    const float* x      = (const float*)d_in[0];
    const float* w_in   = (const float*)d_in[1];
    const float* w_conv = (const float*)d_in[2];
    const float* b_conv = (const float*)d_in[3];
    const float* w_x    = (const float*)d_in[4];
    const float* w_dt   = (const float*)d_in[5];
    const float* b_dt   = (const float*)d_in[6];
    const float* D_skip = (const float*)d_in[7];
    const float* w_out  = (const float*)d_in[8];
    const float* gamma  = (const float*)d_in[9];
    const float* beta   = (const float*)d_in[10];
    float* out = (float*)d_out;

    // fused kernel dynamic smem (> 48KB -> opt-in)
    static int smem_set = 0;
    const int fused_smem = (384 * 32 + 16 * 384 + 384 * 9 + 5 * 384 +
                            WARPS_PER_BLOCK * 384 + WARPS_PER_BLOCK * 32) * 4;
    if (!smem_set) {
        cudaFuncSetAttribute(fused_ssm_kernel,
                             cudaFuncAttributeMaxDynamicSharedMemorySize,
                             fused_smem);
        smem_set = 1;
    }

    // 1. projection GEMM
    dim3 g1(MROWS / G1_BM, NPROJ / G1_BN);
    gemm_proj_kernel<<<g1, 256>>>(x, w_in);

    // 2. fused conv + ssm + layernorm
    const int total_warps = MROWS / ROWS_PER_WARP;          // 16384
    const int blocks2 = total_warps / WARPS_PER_BLOCK;      // 2048
    fused_ssm_kernel<<<blocks2, 256, fused_smem>>>(
        w_conv, b_conv, w_x, w_dt, b_dt, D_skip, gamma, beta);

    // 3. output GEMM with transposed write
    dim3 g3(MROWS / G3_BM, DMODEL / G3_BN);
    gemm_out_kernel<<<g3, 256>>>(w_out, out);
}

// round 2
// speedup vs baseline: 1.0098x; 1.0098x over previous
#include <cuda_runtime.h>
#include <math.h>

// ---------------- problem constants ----------------
#define BATCH     8
#define DMODEL    192
#define DINNER    384
#define DSTATE    16
#define HIMG      128
#define WIMG      128
#define LIMG      16384               // H*W
#define MROWS     131072              // BATCH * LIMG
#define NPROJ     768                 // 2*DINNER

typedef unsigned long long ull;

// ---------------- scratch (static device memory; no allocs allowed) --------
__device__ float g_XI[(size_t)MROWS * DINNER];   // x_inner after proj
__device__ float g_ZS[(size_t)MROWS * DINNER];   // silu(z) after proj
__device__ float g_Y [(size_t)MROWS * DINNER];   // post-layernorm y

// ---------------- f32x2 helpers (sm_103a packed fp32 FMA) ------------------
__device__ __forceinline__ ull fma2(ull a, ull b, ull c) {
    ull d;
    asm("fma.rn.f32x2 %0, %1, %2, %3;" : "=l"(d) : "l"(a), "l"(b), "l"(c));
    return d;
}
__device__ __forceinline__ ull dup2(float x) {
    ull d;
    asm("mov.b64 %0, {%1, %1};" : "=l"(d) : "f"(x));
    return d;
}
__device__ __forceinline__ float lo32(ull v) {
    return __uint_as_float((unsigned)(v & 0xffffffffull));
}
__device__ __forceinline__ float hi32(ull v) {
    return __uint_as_float((unsigned)(v >> 32));
}

// =====================================================================
// Kernel 1: x_proj = x @ w_in ; split -> XI (raw), ZS (silu applied)
// A: [131072,192] row-major, B: [192,768]
// BM=128, BN=128, BK=16, 256 threads, 8x8 micro-tile via f32x2
// mt=tid/16 (16), nt=tid%16 (16); m = bm+mt*8+i, n = bn+nt*2+p*32 (+pair)
// =====================================================================
#define G1_BM 128
#define G1_BN 128
#define G1_BK 16

__global__ void __launch_bounds__(256, 2) gemm_proj_kernel(
    const float* __restrict__ A, const float* __restrict__ Bw)
{
    __shared__ float As[G1_BK][G1_BM + 4];   // 132: float4-aligned rows
    __shared__ float Bs[G1_BK][G1_BN];

    const int tid = threadIdx.x;
    const int bm  = blockIdx.x * G1_BM;
    const int bn  = blockIdx.y * G1_BN;
    const int mt  = tid >> 4;    // 0..15
    const int nt  = tid & 15;    // 0..15

    ull acc2[8][4];
#pragma unroll
    for (int i = 0; i < 8; ++i)
#pragma unroll
        for (int p = 0; p < 4; ++p) acc2[i][p] = 0ull;

    for (int k0 = 0; k0 < DMODEL; k0 += G1_BK) {
        // A tile 128x16 (transpose into As[k][m]): 512 float4, 2/thread
#pragma unroll
        for (int t = 0; t < 2; ++t) {
            const int idx = tid + 256 * t;
            const int r = idx >> 2;
            const int c = (idx & 3) * 4;
            float4 v = *(const float4*)(A + (size_t)(bm + r) * DMODEL + k0 + c);
            As[c + 0][r] = v.x;
            As[c + 1][r] = v.y;
            As[c + 2][r] = v.z;
            As[c + 3][r] = v.w;
        }
        // B tile 16x128: 512 float4, 2/thread
#pragma unroll
        for (int t = 0; t < 2; ++t) {
            const int idx = tid + 256 * t;
            const int r = idx >> 5;
            const int c = (idx & 31) * 4;
            *(float4*)&Bs[r][c] =
                *(const float4*)(Bw + (size_t)(k0 + r) * NPROJ + bn + c);
        }
        __syncthreads();

#pragma unroll
        for (int k = 0; k < G1_BK; ++k) {
            float4 a0 = *(const float4*)&As[k][mt * 8];
            float4 a1 = *(const float4*)&As[k][mt * 8 + 4];
            ull ra2[8];
            ra2[0] = dup2(a0.x); ra2[1] = dup2(a0.y);
            ra2[2] = dup2(a0.z); ra2[3] = dup2(a0.w);
            ra2[4] = dup2(a1.x); ra2[5] = dup2(a1.y);
            ra2[6] = dup2(a1.z); ra2[7] = dup2(a1.w);
            ull rb2[4];
#pragma unroll
            for (int p = 0; p < 4; ++p)
                rb2[p] = *(const ull*)&Bs[k][nt * 2 + p * 32];
#pragma unroll
            for (int i = 0; i < 8; ++i)
#pragma unroll
                for (int p = 0; p < 4; ++p)
                    acc2[i][p] = fma2(ra2[i], rb2[p], acc2[i][p]);
        }
        __syncthreads();
    }

    // epilogue: block column in n decides XI vs ZS (BN=128 divides 384)
#pragma unroll
    for (int i = 0; i < 8; ++i) {
        const size_t m = (size_t)bm + mt * 8 + i;
#pragma unroll
        for (int p = 0; p < 4; ++p) {
            const int n = bn + nt * 2 + p * 32;
            float v0 = lo32(acc2[i][p]);
            float v1 = hi32(acc2[i][p]);
            if (n < DINNER) {
                float2 o = make_float2(v0, v1);
                *(float2*)(g_XI + m * DINNER + n) = o;
            } else {
                float s0 = 1.f / (1.f + expf(-v0));
                float s1 = 1.f / (1.f + expf(-v1));
                float2 o = make_float2(v0 * s0, v1 * s1);
                *(float2*)(g_ZS + m * DINNER + (n - DINNER)) = o;
            }
        }
    }
}

// =====================================================================
// Kernel 2: fused depthwise conv3x3 + silu + SSM + gate + LayerNorm
// One warp per spatial position row; 384 channels -> 12 per lane.
// x_ssm via register partials + butterfly warp reduction.
// =====================================================================
#define CPL 12
#define WARPS_PER_BLOCK 8
#define ROWS_PER_WARP 8
#define WXP 33          // padded row stride for w_x in shared (conflict-free)

__global__ void __launch_bounds__(256) fused_ssm_kernel(
    const float* __restrict__ w_conv,   // [384,1,3,3]
    const float* __restrict__ b_conv,   // [384]
    const float* __restrict__ w_x,      // [384,32]
    const float* __restrict__ w_dt,     // [16,384]
    const float* __restrict__ b_dt,     // [384]
    const float* __restrict__ D_skip,   // [384]
    const float* __restrict__ gamma,    // [384]
    const float* __restrict__ beta)     // [384]
{
    extern __shared__ float sh[];
    float* wx_sh    = sh;                          // 384*33 (padded)
    float* wdt_sh   = wx_sh    + 384 * WXP;        // 16*384
    float* wconv_sh = wdt_sh   + 16 * 384;         // 384*9
    float* bconv_sh = wconv_sh + 384 * 9;          // 384
    float* bdt_sh   = bconv_sh + 384;              // 384
    float* dskip_sh = bdt_sh   + 384;              // 384
    float* gam_sh   = dskip_sh + 384;              // 384
    float* bet_sh   = gam_sh   + 384;              // 384
    float* ssm_sh   = bet_sh   + 384;              // 8*32

    const int tid = threadIdx.x;
    for (int i = tid; i < 384 * 32; i += blockDim.x)
        wx_sh[(i >> 5) * WXP + (i & 31)] = w_x[i];
    for (int i = tid; i < 16 * 384; i += blockDim.x) wdt_sh[i]   = w_dt[i];
    for (int i = tid; i < 384 * 9;  i += blockDim.x) wconv_sh[i] = w_conv[i];
    for (int i = tid; i < 384;      i += blockDim.x) {
        bconv_sh[i] = b_conv[i];
        bdt_sh[i]   = b_dt[i];
        dskip_sh[i] = D_skip[i];
        gam_sh[i]   = gamma[i];
        bet_sh[i]   = beta[i];
    }
    __syncthreads();

    const int warp = tid >> 5;
    const int lane = tid & 31;
    const int gw   = blockIdx.x * WARPS_PER_BLOCK + warp;
    const size_t base_r = (size_t)gw * ROWS_PER_WARP;

    float* ssm_w = ssm_sh + warp * 32;

    for (int it = 0; it < ROWS_PER_WARP; ++it) {
        const size_t r = base_r + it;
        const int l = (int)(r & (LIMG - 1));
        const int h = l >> 7;
        const int w = l & 127;

        // ---- 1. depthwise conv 3x3 + silu (registers only) ----
        float xc_reg[CPL];
#pragma unroll
        for (int k = 0; k < CPL; ++k) {
            const int ch = lane + k * 32;
            float acc = bconv_sh[ch];
#pragma unroll
            for (int dy = -1; dy <= 1; ++dy) {
                const int hh = h + dy;
                if (hh < 0 || hh >= HIMG) continue;
#pragma unroll
                for (int dx = -1; dx <= 1; ++dx) {
                    const int ww = w + dx;
                    if (ww < 0 || ww >= WIMG) continue;
                    const size_t rr = r + (size_t)(dy * WIMG + dx);
                    acc += wconv_sh[ch * 9 + (dy + 1) * 3 + (dx + 1)]
                           * g_XI[rr * DINNER + ch];
                }
            }
            const float s = 1.f / (1.f + expf(-acc));
            xc_reg[k] = acc * s;
        }

        // ---- 2. x_ssm partials in registers ----
        float part[32];
#pragma unroll
        for (int s = 0; s < 32; ++s) part[s] = 0.f;
#pragma unroll
        for (int k = 0; k < CPL; ++k) {
            const int ch = lane + k * 32;
            const float xv = xc_reg[k];
            const float* wrow = wx_sh + ch * WXP;
#pragma unroll
            for (int s = 0; s < 32; ++s)
                part[s] = fmaf(xv, wrow[s], part[s]);
        }
        // butterfly: reduce 32 partial arrays across 32 lanes;
        // lane ends holding sum for state == lane
#define RED_ROUND(STEP, M)                                                   \
        {                                                                    \
            const bool hib = (lane & (STEP)) != 0;                           \
            _Pragma("unroll")                                                \
            for (int i = 0; i < (M); ++i) {                                  \
                float keep = hib ? part[2 * i + 1] : part[2 * i];            \
                float send = hib ? part[2 * i] : part[2 * i + 1];            \
                part[i] = keep + __shfl_xor_sync(0xffffffffu, send, (STEP)); \
            }                                                                \
        }
        RED_ROUND(1, 16)
        RED_ROUND(2, 8)
        RED_ROUND(4, 4)
        RED_ROUND(8, 2)
        RED_ROUND(16, 1)
#undef RED_ROUND

        ssm_w[lane] = part[0];
        __syncwarp();

        // ---- 3. bc = sum_s B_s * C_s ----
        float Bst[DSTATE];
        float bc = 0.f;
#pragma unroll
        for (int s = 0; s < DSTATE; ++s) {
            Bst[s] = ssm_w[s];
            bc = fmaf(Bst[s], ssm_w[DSTATE + s], bc);
        }

        // ---- 4. dt, gate, accumulate stats ----
        float yv[CPL];
        float sum = 0.f, sumsq = 0.f;
#pragma unroll
        for (int k = 0; k < CPL; ++k) {
            const int ch = lane + k * 32;
            float dv = bdt_sh[ch];
#pragma unroll
            for (int s = 0; s < DSTATE; ++s)
                dv = fmaf(Bst[s], wdt_sh[s * 384 + ch], dv);
            const float dt = (dv > 20.f) ? dv : log1pf(expf(dv));
            const float zs = g_ZS[r * DINNER + ch];
            const float v  = (dt * bc + xc_reg[k] * dskip_sh[ch]) * zs;
            yv[k] = v;
            sum   += v;
            sumsq += v * v;
        }
#pragma unroll
        for (int o = 16; o; o >>= 1) {
            sum   += __shfl_xor_sync(0xffffffffu, sum, o);
            sumsq += __shfl_xor_sync(0xffffffffu, sumsq, o);
        }
        const float mu  = sum * (1.f / 384.f);
        const float var = sumsq * (1.f / 384.f) - mu * mu;
        const float rs  = rsqrtf(var + 1e-5f);

        // ---- 5. layernorm + store ----
#pragma unroll
        for (int k = 0; k < CPL; ++k) {
            const int ch = lane + k * 32;
            g_Y[r * DINNER + ch] = (yv[k] - mu) * rs * gam_sh[ch] + bet_sh[ch];
        }
    }
}

// =====================================================================
// Kernel 3: out = Y @ w_out, written transposed as [B, 192, L]
// BM=128, BN=64, BK=16, 256 threads; 4m x 8n micro (n pairs via f32x2).
// mt=tid%32 follows m/l (coalesced transposed write), nt=tid/32 (8).
// =====================================================================
#define G3_BM 128
#define G3_BN 64
#define G3_BK 16

__global__ void __launch_bounds__(256, 2) gemm_out_kernel(
    const float* __restrict__ Bw,   // w_out [384,192]
    float* __restrict__ OUT)        // [8,192,16384]
{
    __shared__ float As[G3_BK][G3_BM + 1];
    __shared__ float Bs[G3_BK][G3_BN];

    const int tid = threadIdx.x;
    const size_t bm = (size_t)blockIdx.x * G3_BM;
    const int bn    = blockIdx.y * G3_BN;
    const int mt = tid & 31;
    const int nt = tid >> 5;

    ull acc2[4][4];
#pragma unroll
    for (int i = 0; i < 4; ++i)
#pragma unroll
        for (int j = 0; j < 4; ++j) acc2[i][j] = 0ull;

    for (int k0 = 0; k0 < DINNER; k0 += G3_BK) {
        // A tile 128x16 transposed: 512 float4, 2/thread
#pragma unroll
        for (int t = 0; t < 2; ++t) {
            const int idx = tid + 256 * t;
            const int r = idx >> 2;
            const int c = (idx & 3) * 4;
            float4 v = *(const float4*)(g_Y + (bm + r) * DINNER + k0 + c);
            As[c + 0][r] = v.x;
            As[c + 1][r] = v.y;
            As[c + 2][r] = v.z;
            As[c + 3][r] = v.w;
        }
        // B tile 16x64 = 256 float4, 1/thread
        {
            const int r = tid >> 4;
            const int c = (tid & 15) * 4;
            *(float4*)&Bs[r][c] =
                *(const float4*)(Bw + (size_t)(k0 + r) * DMODEL + bn + c);
        }
        __syncthreads();

#pragma unroll
        for (int k = 0; k < G3_BK; ++k) {
            ull rb2[4];
#pragma unroll
            for (int j = 0; j < 4; ++j)
                rb2[j] = *(const ull*)&Bs[k][nt * 8 + j * 2];
            ull ra2[4];
#pragma unroll
            for (int i = 0; i < 4; ++i)
                ra2[i] = dup2(As[k][mt + i * 32]);
#pragma unroll
            for (int i = 0; i < 4; ++i)
#pragma unroll
                for (int j = 0; j < 4; ++j)
                    acc2[i][j] = fma2(ra2[i], rb2[j], acc2[i][j]);
        }
        __syncthreads();
    }

    // transposed write: OUT[b][n][l]; lanes (mt) contiguous in l -> coalesced
#pragma unroll
    for (int i = 0; i < 4; ++i) {
        const size_t m = bm + mt + i * 32;
        const int b = (int)(m >> 14);
        const int l = (int)(m & 16383);
#pragma unroll
        for (int j = 0; j < 4; ++j) {
            const int n = bn + nt * 8 + j * 2;
            OUT[((size_t)b * DMODEL + n)     * LIMG + l] = lo32(acc2[i][j]);
            OUT[((size_t)b * DMODEL + n + 1) * LIMG + l] = hi32(acc2[i][j]);
        }
    }
}

// =====================================================================
extern "C" void kernel_launch(void* const* d_in, const int* in_sizes, int n_in,
                              void* d_out, int out_size) {
    (void)in_sizes; (void)n_in; (void)out_size;
    const float* x      = (const float*)d_in[0];
    const float* w_in   = (const float*)d_in[1];
    const float* w_conv = (const float*)d_in[2];
    const float* b_conv = (const float*)d_in[3];
    const float* w_x    = (const float*)d_in[4];
    const float* w_dt   = (const float*)d_in[5];
    const float* b_dt   = (const float*)d_in[6];
    const float* D_skip = (const float*)d_in[7];
    const float* w_out  = (const float*)d_in[8];
    const float* gamma  = (const float*)d_in[9];
    const float* beta   = (const float*)d_in[10];
    float* out = (float*)d_out;

    const int fused_smem = (384 * WXP + 16 * 384 + 384 * 9 + 5 * 384 +
                            WARPS_PER_BLOCK * 32) * 4;
    cudaFuncSetAttribute(fused_ssm_kernel,
                         cudaFuncAttributeMaxDynamicSharedMemorySize,
                         fused_smem);

    // 1. projection GEMM
    dim3 g1(MROWS / G1_BM, NPROJ / G1_BN);
    gemm_proj_kernel<<<g1, 256>>>(x, w_in);

    // 2. fused conv + ssm + layernorm
    const int total_warps = MROWS / ROWS_PER_WARP;          // 16384
    const int blocks2 = total_warps / WARPS_PER_BLOCK;      // 2048
    fused_ssm_kernel<<<blocks2, 256, fused_smem>>>(
        w_conv, b_conv, w_x, w_dt, b_dt, D_skip, gamma, beta);

    // 3. output GEMM with transposed write
    dim3 g3(MROWS / G3_BM, DMODEL / G3_BN);
    gemm_out_kernel<<<g3, 256>>>(w_out, out);
}

// round 3
// speedup vs baseline: 1.4796x; 1.4652x over previous
#include <cuda_runtime.h>
#include <math.h>

// ---------------- problem constants ----------------
#define BATCH     8
#define DMODEL    192
#define DINNER    384
#define DSTATE    16
#define HIMG      128
#define WIMG      128
#define LIMG      16384
#define MROWS     131072
#define NPROJ     768

typedef unsigned long long ull;

// ---------------- scratch (static device memory) ---------------------------
__device__ float g_XI  [(size_t)MROWS * DINNER];   // x_inner after proj
__device__ float g_ZS  [(size_t)MROWS * DINNER];   // silu(z)
__device__ float g_XC  [(size_t)MROWS * DINNER];   // conv+silu output
__device__ float g_Y   [(size_t)MROWS * DINNER];   // post-LN y
__device__ float g_XSSM[(size_t)MROWS * 32];       // [B_ssm | C_ssm]

// ---------------- f32x2 helpers ------------------------------------------
__device__ __forceinline__ ull fma2(ull a, ull b, ull c) {
    ull d;
    asm("fma.rn.f32x2 %0, %1, %2, %3;" : "=l"(d) : "l"(a), "l"(b), "l"(c));
    return d;
}
__device__ __forceinline__ ull dup2(float x) {
    ull d;
    asm("mov.b64 %0, {%1, %1};" : "=l"(d) : "f"(x));
    return d;
}
__device__ __forceinline__ float lo32(ull v) {
    return __uint_as_float((unsigned)(v & 0xffffffffull));
}
__device__ __forceinline__ float hi32(ull v) {
    return __uint_as_float((unsigned)(v >> 32));
}
__device__ __forceinline__ float silu_f(float v) {
    return v * __fdividef(1.f, 1.f + expf(-v));
}
__device__ __forceinline__ float softplus_f(float v) {
    return (v > 15.f) ? v : __logf(1.f + expf(v));
}

// =====================================================================
// Kernel 1: x_proj = x @ w_in ; split -> XI (raw), ZS (silu)   [unchanged]
// =====================================================================
#define G1_BM 128
#define G1_BN 128
#define G1_BK 16

__global__ void __launch_bounds__(256, 2) gemm_proj_kernel(
    const float* __restrict__ A, const float* __restrict__ Bw)
{
    __shared__ float As[G1_BK][G1_BM + 4];
    __shared__ float Bs[G1_BK][G1_BN];

    const int tid = threadIdx.x;
    const int bm  = blockIdx.x * G1_BM;
    const int bn  = blockIdx.y * G1_BN;
    const int mt  = tid >> 4;
    const int nt  = tid & 15;

    ull acc2[8][4];
#pragma unroll
    for (int i = 0; i < 8; ++i)
#pragma unroll
        for (int p = 0; p < 4; ++p) acc2[i][p] = 0ull;

    for (int k0 = 0; k0 < DMODEL; k0 += G1_BK) {
#pragma unroll
        for (int t = 0; t < 2; ++t) {
            const int idx = tid + 256 * t;
            const int r = idx >> 2;
            const int c = (idx & 3) * 4;
            float4 v = *(const float4*)(A + (size_t)(bm + r) * DMODEL + k0 + c);
            As[c + 0][r] = v.x;
            As[c + 1][r] = v.y;
            As[c + 2][r] = v.z;
            As[c + 3][r] = v.w;
        }
#pragma unroll
        for (int t = 0; t < 2; ++t) {
            const int idx = tid + 256 * t;
            const int r = idx >> 5;
            const int c = (idx & 31) * 4;
            *(float4*)&Bs[r][c] =
                *(const float4*)(Bw + (size_t)(k0 + r) * NPROJ + bn + c);
        }
        __syncthreads();

#pragma unroll
        for (int k = 0; k < G1_BK; ++k) {
            float4 a0 = *(const float4*)&As[k][mt * 8];
            float4 a1 = *(const float4*)&As[k][mt * 8 + 4];
            ull ra2[8];
            ra2[0] = dup2(a0.x); ra2[1] = dup2(a0.y);
            ra2[2] = dup2(a0.z); ra2[3] = dup2(a0.w);
            ra2[4] = dup2(a1.x); ra2[5] = dup2(a1.y);
            ra2[6] = dup2(a1.z); ra2[7] = dup2(a1.w);
            ull rb2[4];
#pragma unroll
            for (int p = 0; p < 4; ++p)
                rb2[p] = *(const ull*)&Bs[k][nt * 2 + p * 32];
#pragma unroll
            for (int i = 0; i < 8; ++i)
#pragma unroll
                for (int p = 0; p < 4; ++p)
                    acc2[i][p] = fma2(ra2[i], rb2[p], acc2[i][p]);
        }
        __syncthreads();
    }

#pragma unroll
    for (int i = 0; i < 8; ++i) {
        const size_t m = (size_t)bm + mt * 8 + i;
#pragma unroll
        for (int p = 0; p < 4; ++p) {
            const int n = bn + nt * 2 + p * 32;
            float v0 = lo32(acc2[i][p]);
            float v1 = hi32(acc2[i][p]);
            if (n < DINNER) {
                *(float2*)(g_XI + m * DINNER + n) = make_float2(v0, v1);
            } else {
                *(float2*)(g_ZS + m * DINNER + (n - DINNER)) =
                    make_float2(silu_f(v0), silu_f(v1));
            }
        }
    }
}

// =====================================================================
// Kernel 2: tiled depthwise conv 3x3 + silu : XI -> XC
// Tile: 16x16 spatial x 64 channels. smem halo 18x18x64.
// grid: (cg=6, tx=8, b*8+ty=64)
// =====================================================================
__global__ void __launch_bounds__(256) conv_kernel(
    const float* __restrict__ w_conv, const float* __restrict__ b_conv)
{
    extern __shared__ float csh[];
    float* in_sh = csh;                    // 324*64
    float* wt_sh = in_sh + 324 * 64;       // 9*64 (tap-major)
    float* bb_sh = wt_sh + 9 * 64;         // 64

    const int cg = blockIdx.x;
    const int tx = blockIdx.y;
    const int bz = blockIdx.z;
    const int b  = bz >> 3;
    const int ty = bz & 7;
    const int h0 = ty * 16;
    const int w0 = tx * 16;
    const int tid = threadIdx.x;

    for (int i = tid; i < 9 * 64; i += 256) {
        int tap = i >> 6, c = i & 63;
        wt_sh[i] = w_conv[(cg * 64 + c) * 9 + tap];
    }
    if (tid < 64) bb_sh[tid] = b_conv[cg * 64 + tid];

    // halo load: 18x18 positions x 16 float4
    for (int i = tid; i < 324 * 16; i += 256) {
        const int pos = i >> 4;
        const int c4  = i & 15;
        const int y = pos / 18;
        const int x = pos - y * 18;
        const int gh = h0 + y - 1;
        const int gw = w0 + x - 1;
        float4 v = make_float4(0.f, 0.f, 0.f, 0.f);
        if (gh >= 0 && gh < HIMG && gw >= 0 && gw < WIMG) {
            const size_t row = ((size_t)b << 14) + (gh << 7) + gw;
            v = *(const float4*)(g_XI + row * DINNER + cg * 64 + c4 * 4);
        }
        *(float4*)(in_sh + (size_t)pos * 64 + c4 * 4) = v;
    }
    __syncthreads();

    const int x  = tid >> 4;      // 0..15
    const int c4 = tid & 15;      // 0..15
    float4 wr[9];
#pragma unroll
    for (int t = 0; t < 9; ++t)
        wr[t] = *(float4*)(wt_sh + t * 64 + c4 * 4);
    const float4 bias = *(float4*)(bb_sh + c4 * 4);

#pragma unroll 4
    for (int y = 0; y < 16; ++y) {
        float4 acc = bias;
#pragma unroll
        for (int dy = 0; dy < 3; ++dy)
#pragma unroll
            for (int dx = 0; dx < 3; ++dx) {
                float4 v = *(float4*)(in_sh +
                    (size_t)((y + dy) * 18 + x + dx) * 64 + c4 * 4);
                const float4 w = wr[dy * 3 + dx];
                acc.x = fmaf(v.x, w.x, acc.x);
                acc.y = fmaf(v.y, w.y, acc.y);
                acc.z = fmaf(v.z, w.z, acc.z);
                acc.w = fmaf(v.w, w.w, acc.w);
            }
        acc.x = silu_f(acc.x);
        acc.y = silu_f(acc.y);
        acc.z = silu_f(acc.z);
        acc.w = silu_f(acc.w);
        const size_t row = ((size_t)b << 14) + ((h0 + y) << 7) + (w0 + x);
        *(float4*)(g_XC + row * DINNER + cg * 64 + c4 * 4) = acc;
    }
}

// =====================================================================
// Kernel 3: XSSM = XC @ w_x   (M=131072, N=32, K=384)
// BM=128, BK=64. Thread micro: 2 rows x 8 states.
// =====================================================================
#define XS_BM 128
#define XS_BK 64
#define XS_PAD 68

__global__ void __launch_bounds__(256) xssm_kernel(
    const float* __restrict__ w_x)
{
    extern __shared__ float xsh[];
    float* wx_sh = xsh;                 // 384*32
    float* As    = wx_sh + 384 * 32;    // 128*68

    const int tid = threadIdx.x;
    for (int i = tid; i < 384 * 32 / 4; i += 256)
        *(float4*)(wx_sh + i * 4) = *(const float4*)(w_x + i * 4);

    const size_t bm = (size_t)blockIdx.x * XS_BM;
    const int mt = tid >> 2;       // 0..63 -> rows mt*2+{0,1}
    const int nt = tid & 3;        // 0..3  -> states nt*8..+7

    float acc[2][8];
#pragma unroll
    for (int i = 0; i < 2; ++i)
#pragma unroll
        for (int j = 0; j < 8; ++j) acc[i][j] = 0.f;

    for (int kc = 0; kc < DINNER; kc += XS_BK) {
        if (kc) __syncthreads();
        for (int i = tid; i < 128 * 16; i += 256) {
            const int row = i >> 4;
            const int c4b = i & 15;
            float4 v = *(const float4*)(g_XC + (bm + row) * DINNER + kc + c4b * 4);
            *(float4*)(As + row * XS_PAD + c4b * 4) = v;
        }
        __syncthreads();

#pragma unroll
        for (int k = 0; k < XS_BK; ++k) {
            const float a0 = As[(mt * 2 + 0) * XS_PAD + k];
            const float a1 = As[(mt * 2 + 1) * XS_PAD + k];
            float4 b0 = *(float4*)(wx_sh + (kc + k) * 32 + nt * 8);
            float4 b1 = *(float4*)(wx_sh + (kc + k) * 32 + nt * 8 + 4);
            acc[0][0] = fmaf(a0, b0.x, acc[0][0]);
            acc[0][1] = fmaf(a0, b0.y, acc[0][1]);
            acc[0][2] = fmaf(a0, b0.z, acc[0][2]);
            acc[0][3] = fmaf(a0, b0.w, acc[0][3]);
            acc[0][4] = fmaf(a0, b1.x, acc[0][4]);
            acc[0][5] = fmaf(a0, b1.y, acc[0][5]);
            acc[0][6] = fmaf(a0, b1.z, acc[0][6]);
            acc[0][7] = fmaf(a0, b1.w, acc[0][7]);
            acc[1][0] = fmaf(a1, b0.x, acc[1][0]);
            acc[1][1] = fmaf(a1, b0.y, acc[1][1]);
            acc[1][2] = fmaf(a1, b0.z, acc[1][2]);
            acc[1][3] = fmaf(a1, b0.w, acc[1][3]);
            acc[1][4] = fmaf(a1, b1.x, acc[1][4]);
            acc[1][5] = fmaf(a1, b1.y, acc[1][5]);
            acc[1][6] = fmaf(a1, b1.z, acc[1][6]);
            acc[1][7] = fmaf(a1, b1.w, acc[1][7]);
        }
    }

#pragma unroll
    for (int i = 0; i < 2; ++i) {
        const size_t r = bm + mt * 2 + i;
        *(float4*)(g_XSSM + r * 32 + nt * 8) =
            make_float4(acc[i][0], acc[i][1], acc[i][2], acc[i][3]);
        *(float4*)(g_XSSM + r * 32 + nt * 8 + 4) =
            make_float4(acc[i][4], acc[i][5], acc[i][6], acc[i][7]);
    }
}

// =====================================================================
// Kernel 4: pointwise  bc + dt + gate + LayerNorm -> Y
// warp per 2 rows at a time (amortize w_dt smem reads), 2 iterations.
// lane owns channels 4*lane + 128*k (k=0..2) as float4.
// =====================================================================
__global__ void __launch_bounds__(256) point_kernel(
    const float* __restrict__ w_dt,   // [16,384]
    const float* __restrict__ b_dt,
    const float* __restrict__ D_skip,
    const float* __restrict__ gamma,
    const float* __restrict__ beta)
{
    __shared__ float4 wdt4[16 * 96];
    __shared__ float4 bdt4[96], dsk4[96], gam4[96], bet4[96];

    const int tid = threadIdx.x;
    for (int i = tid; i < 16 * 96; i += 256)
        wdt4[i] = ((const float4*)w_dt)[i];
    if (tid < 96) {
        bdt4[tid] = ((const float4*)b_dt)[tid];
        dsk4[tid] = ((const float4*)D_skip)[tid];
        gam4[tid] = ((const float4*)gamma)[tid];
        bet4[tid] = ((const float4*)beta)[tid];
    }
    __syncthreads();

    const int warp = tid >> 5;
    const int lane = tid & 31;
    const size_t wbase = ((size_t)blockIdx.x * 8 + warp) * 4;

#pragma unroll 1
    for (int it = 0; it < 2; ++it) {
        const size_t ra = wbase + it * 2;
        const size_t rb = ra + 1;

        const float va = g_XSSM[ra * 32 + lane];
        const float vb = g_XSSM[rb * 32 + lane];

        float pa = va * __shfl_xor_sync(0xffffffffu, va, 16);
        float pb = vb * __shfl_xor_sync(0xffffffffu, vb, 16);
#pragma unroll
        for (int o = 8; o; o >>= 1) {
            pa += __shfl_xor_sync(0xffffffffu, pa, o);
            pb += __shfl_xor_sync(0xffffffffu, pb, o);
        }
        const float bca = pa, bcb = pb;

        float Ba[DSTATE], Bb[DSTATE];
#pragma unroll
        for (int s = 0; s < DSTATE; ++s) {
            Ba[s] = __shfl_sync(0xffffffffu, va, s);
            Bb[s] = __shfl_sync(0xffffffffu, vb, s);
        }

        float4 ya[3], yb[3];
        float sa = 0.f, sqa = 0.f, sb = 0.f, sqb = 0.f;
#pragma unroll
        for (int k = 0; k < 3; ++k) {
            const int cf = lane + 32 * k;   // float4 channel index
            float4 dva = bdt4[cf];
            float4 dvb = dva;
#pragma unroll
            for (int s = 0; s < DSTATE; ++s) {
                const float4 w = wdt4[s * 96 + cf];
                dva.x = fmaf(Ba[s], w.x, dva.x);
                dva.y = fmaf(Ba[s], w.y, dva.y);
                dva.z = fmaf(Ba[s], w.z, dva.z);
                dva.w = fmaf(Ba[s], w.w, dva.w);
                dvb.x = fmaf(Bb[s], w.x, dvb.x);
                dvb.y = fmaf(Bb[s], w.y, dvb.y);
                dvb.z = fmaf(Bb[s], w.z, dvb.z);
                dvb.w = fmaf(Bb[s], w.w, dvb.w);
            }
            const float4 dsk = dsk4[cf];
            const float4 xca = *(const float4*)(g_XC + ra * DINNER + cf * 4);
            const float4 xcb = *(const float4*)(g_XC + rb * DINNER + cf * 4);
            const float4 zsa = *(const float4*)(g_ZS + ra * DINNER + cf * 4);
            const float4 zsb = *(const float4*)(g_ZS + rb * DINNER + cf * 4);

            float4 v;
            v.x = (softplus_f(dva.x) * bca + xca.x * dsk.x) * zsa.x;
            v.y = (softplus_f(dva.y) * bca + xca.y * dsk.y) * zsa.y;
            v.z = (softplus_f(dva.z) * bca + xca.z * dsk.z) * zsa.z;
            v.w = (softplus_f(dva.w) * bca + xca.w * dsk.w) * zsa.w;
            ya[k] = v;
            sa  += v.x + v.y + v.z + v.w;
            sqa += v.x * v.x + v.y * v.y + v.z * v.z + v.w * v.w;

            v.x = (softplus_f(dvb.x) * bcb + xcb.x * dsk.x) * zsb.x;
            v.y = (softplus_f(dvb.y) * bcb + xcb.y * dsk.y) * zsb.y;
            v.z = (softplus_f(dvb.z) * bcb + xcb.z * dsk.z) * zsb.z;
            v.w = (softplus_f(dvb.w) * bcb + xcb.w * dsk.w) * zsb.w;
            yb[k] = v;
            sb  += v.x + v.y + v.z + v.w;
            sqb += v.x * v.x + v.y * v.y + v.z * v.z + v.w * v.w;
        }

#pragma unroll
        for (int o = 16; o; o >>= 1) {
            sa  += __shfl_xor_sync(0xffffffffu, sa, o);
            sqa += __shfl_xor_sync(0xffffffffu, sqa, o);
            sb  += __shfl_xor_sync(0xffffffffu, sb, o);
            sqb += __shfl_xor_sync(0xffffffffu, sqb, o);
        }
        const float mua = sa * (1.f / 384.f);
        const float rsa = rsqrtf(sqa * (1.f / 384.f) - mua * mua + 1e-5f);
        const float mub = sb * (1.f / 384.f);
        const float rsb = rsqrtf(sqb * (1.f / 384.f) - mub * mub + 1e-5f);

#pragma unroll
        for (int k = 0; k < 3; ++k) {
            const int cf = lane + 32 * k;
            const float4 g = gam4[cf];
            const float4 be = bet4[cf];
            float4 o;
            o.x = (ya[k].x - mua) * rsa * g.x + be.x;
            o.y = (ya[k].y - mua) * rsa * g.y + be.y;
            o.z = (ya[k].z - mua) * rsa * g.z + be.z;
            o.w = (ya[k].w - mua) * rsa * g.w + be.w;
            *(float4*)(g_Y + ra * DINNER + cf * 4) = o;
            o.x = (yb[k].x - mub) * rsb * g.x + be.x;
            o.y = (yb[k].y - mub) * rsb * g.y + be.y;
            o.z = (yb[k].z - mub) * rsb * g.z + be.z;
            o.w = (yb[k].w - mub) * rsb * g.w + be.w;
            *(float4*)(g_Y + rb * DINNER + cf * 4) = o;
        }
    }
}

// =====================================================================
// Kernel 5: out = Y @ w_out, transposed write [B,192,L]   [unchanged]
// =====================================================================
#define G3_BM 128
#define G3_BN 64
#define G3_BK 16

__global__ void __launch_bounds__(256, 2) gemm_out_kernel(
    const float* __restrict__ Bw, float* __restrict__ OUT)
{
    __shared__ float As[G3_BK][G3_BM + 1];
    __shared__ float Bs[G3_BK][G3_BN];

    const int tid = threadIdx.x;
    const size_t bm = (size_t)blockIdx.x * G3_BM;
    const int bn    = blockIdx.y * G3_BN;
    const int mt = tid & 31;
    const int nt = tid >> 5;

    ull acc2[4][4];
#pragma unroll
    for (int i = 0; i < 4; ++i)
#pragma unroll
        for (int j = 0; j < 4; ++j) acc2[i][j] = 0ull;

    for (int k0 = 0; k0 < DINNER; k0 += G3_BK) {
#pragma unroll
        for (int t = 0; t < 2; ++t) {
            const int idx = tid + 256 * t;
            const int r = idx >> 2;
            const int c = (idx & 3) * 4;
            float4 v = *(const float4*)(g_Y + (bm + r) * DINNER + k0 + c);
            As[c + 0][r] = v.x;
            As[c + 1][r] = v.y;
            As[c + 2][r] = v.z;
            As[c + 3][r] = v.w;
        }
        {
            const int r = tid >> 4;
            const int c = (tid & 15) * 4;
            *(float4*)&Bs[r][c] =
                *(const float4*)(Bw + (size_t)(k0 + r) * DMODEL + bn + c);
        }
        __syncthreads();

#pragma unroll
        for (int k = 0; k < G3_BK; ++k) {
            ull rb2[4];
#pragma unroll
            for (int j = 0; j < 4; ++j)
                rb2[j] = *(const ull*)&Bs[k][nt * 8 + j * 2];
            ull ra2[4];
#pragma unroll
            for (int i = 0; i < 4; ++i)
                ra2[i] = dup2(As[k][mt + i * 32]);
#pragma unroll
            for (int i = 0; i < 4; ++i)
#pragma unroll
                for (int j = 0; j < 4; ++j)
                    acc2[i][j] = fma2(ra2[i], rb2[j], acc2[i][j]);
        }
        __syncthreads();
    }

#pragma unroll
    for (int i = 0; i < 4; ++i) {
        const size_t m = bm + mt + i * 32;
        const int b = (int)(m >> 14);
        const int l = (int)(m & 16383);
#pragma unroll
        for (int j = 0; j < 4; ++j) {
            const int n = bn + nt * 8 + j * 2;
            OUT[((size_t)b * DMODEL + n)     * LIMG + l] = lo32(acc2[i][j]);
            OUT[((size_t)b * DMODEL + n + 1) * LIMG + l] = hi32(acc2[i][j]);
        }
    }
}

// =====================================================================
extern "C" void kernel_launch(void* const* d_in, const int* in_sizes, int n_in,
                              void* d_out, int out_size) {
    (void)in_sizes; (void)n_in; (void)out_size;
    const float* x      = (const float*)d_in[0];
    const float* w_in   = (const float*)d_in[1];
    const float* w_conv = (const float*)d_in[2];
    const float* b_conv = (const float*)d_in[3];
    const float* w_x    = (const float*)d_in[4];
    const float* w_dt   = (const float*)d_in[5];
    const float* b_dt   = (const float*)d_in[6];
    const float* D_skip = (const float*)d_in[7];
    const float* w_out  = (const float*)d_in[8];
    const float* gamma  = (const float*)d_in[9];
    const float* beta   = (const float*)d_in[10];
    float* out = (float*)d_out;

    const int conv_smem = (324 * 64 + 9 * 64 + 64) * 4;           // ~85.4 KB
    const int xssm_smem = (384 * 32 + 128 * XS_PAD) * 4;          // ~84 KB
    cudaFuncSetAttribute(conv_kernel,
        cudaFuncAttributeMaxDynamicSharedMemorySize, conv_smem);
    cudaFuncSetAttribute(xssm_kernel,
        cudaFuncAttributeMaxDynamicSharedMemorySize, xssm_smem);

    // 1. projection GEMM
    dim3 g1(MROWS / G1_BM, NPROJ / G1_BN);
    gemm_proj_kernel<<<g1, 256>>>(x, w_in);

    // 2. depthwise conv + silu
    dim3 g2(6, 8, 64);
    conv_kernel<<<g2, 256, conv_smem>>>(w_conv, b_conv);

    // 3. XSSM small GEMM
    xssm_kernel<<<MROWS / XS_BM, 256, xssm_smem>>>(w_x);

    // 4. pointwise dt/gate/LN
    point_kernel<<<MROWS / 32, 256>>>(w_dt, b_dt, D_skip, gamma, beta);

    // 5. output GEMM (transposed write)
    dim3 g3(MROWS / G3_BM, DMODEL / G3_BN);
    gemm_out_kernel<<<g3, 256>>>(w_out, out);
}